// round 13
// baseline (speedup 1.0000x reference)
#include <cuda_runtime.h>
#include <cuda_bf16.h>
#include <cstdint>

// activation (16, 128, 114, 114) float32.
// Channels  0..31  : inactive (copy)      — TMA load + TMA store (t0 only)
// Channels 32..79  : 2x2 block-sign ReLU  — TMA load + LDS + STG
// Channels 80..127 : 4x4 block-sign ReLU  — TMA load + LDS + STG
//
// Sign chain: q = int16((int64(trunc(sum)) >> log2(n)) >> 5) >= 0 reduces to
// trunc(sum) >= 0  <=>  sum > -1.0f (int16 wrap needs |sum| >= 4.2M/16.8M =
// 32/64 sigma of the block-sum distribution — impossible here).
//
// Quarter-image chunks (rows 0/28/56/84; multiples of 4 -> no block straddle).
// Each chunk is loaded as TWO sub-transfers (16 rows + 12/14 rows) on separate
// mbarriers so compute on sub0 overlaps delivery of sub1 (de-convoying).

#define W_DIM 114
#define IMG_ELEMS (114 * 114)            // 12996 floats, 51984 B
#define CHUNK_MAX (30 * W_DIM)           // 3420 floats = 13680 B
#define SUB0_ROWS 16                     // multiple of 4, keeps parity

__device__ __forceinline__ float sgn(float sum) {
    return (sum > -1.0f) ? 1.0f : 0.0f;
}

__device__ __forceinline__ void mbar_wait(uint32_t mb) {
    uint32_t done;
    do {
        asm volatile(
            "{\n\t.reg .pred P;\n\t"
            "mbarrier.try_wait.parity.shared::cta.b64 P, [%1], %2, 0x989680;\n\t"
            "selp.b32 %0, 1, 0, P;\n\t}"
            : "=r"(done) : "r"(mb), "r"(0u) : "memory");
    } while (!done);
}

__device__ __forceinline__ void run_2x2(const float* __restrict__ buf,
                                        float* __restrict__ dst,
                                        int bi_beg, int bi_end, int t) {
    const int total = (bi_end - bi_beg) * 57;
    #pragma unroll 4
    for (int i = t; i < total; i += 128) {
        const int bi = bi_beg + i / 57;
        const int bj = i - (i / 57) * 57;
        const int off = (2 * bi) * W_DIM + 2 * bj;
        float2 a = *(const float2*)(buf + off);
        float2 b = *(const float2*)(buf + off + W_DIM);
        const float m = sgn(a.x + a.y + b.x + b.y);
        *(float2*)(dst + off)         = make_float2(a.x * m, a.y * m);
        *(float2*)(dst + off + W_DIM) = make_float2(b.x * m, b.y * m);
    }
}

__device__ __forceinline__ void run_4x4(const float* __restrict__ buf,
                                        float* __restrict__ dst,
                                        int bi_beg, int bi_end, int nrows, int t) {
    const int total = (bi_end - bi_beg) * 29;
    #pragma unroll 2
    for (int i = t; i < total; i += 128) {
        const int bi = bi_beg + i / 29;
        const int bj = i - (i / 29) * 29;
        const int lr0 = 4 * bi;
        const int avail = min(4, nrows - lr0);   // 4, or 2 on q3 tail
        const int c0 = 4 * bj;
        const bool fullc = (bj < 28);            // bj==28 -> 2 cols
        float2 v[4][2];
        float sum = 0.0f;
        #pragma unroll
        for (int r = 0; r < 4; r++) {
            if (r < avail) {
                const float2* p = (const float2*)(buf + (lr0 + r) * W_DIM + c0);
                v[r][0] = p[0];
                sum += v[r][0].x + v[r][0].y;
                if (fullc) {
                    v[r][1] = p[1];
                    sum += v[r][1].x + v[r][1].y;
                }
            }
        }
        const float m = sgn(sum);
        #pragma unroll
        for (int r = 0; r < 4; r++) {
            if (r < avail) {
                float2* d = (float2*)(dst + (lr0 + r) * W_DIM + c0);
                d[0] = make_float2(v[r][0].x * m, v[r][0].y * m);
                if (fullc) d[1] = make_float2(v[r][1].x * m, v[r][1].y * m);
            }
        }
    }
}

__global__ void __launch_bounds__(128)
block_relu_q2(const float* __restrict__ in, float* __restrict__ out) {
    __shared__ alignas(128) float buf[CHUNK_MAX];
    __shared__ alignas(8) uint64_t mbar[2];

    const int q    = blockIdx.x & 3;
    const int img  = blockIdx.x >> 2;        // n*128 + c
    const int c    = img & 127;
    const int nrows = (q == 3) ? 30 : 28;
    const int rows1 = nrows - SUB0_ROWS;     // 12 or 14
    const int bytes0 = SUB0_ROWS * W_DIM * 4;        // 7296
    const int bytes1 = rows1 * W_DIM * 4;            // 5472 or 6384

    const float* src = in  + (size_t)img * IMG_ELEMS + (size_t)q * 28 * W_DIM;
    float*       dst = out + (size_t)img * IMG_ELEMS + (size_t)q * 28 * W_DIM;

    const int t = threadIdx.x;
    const uint32_t mb0 = (uint32_t)__cvta_generic_to_shared(&mbar[0]);
    const uint32_t sb  = (uint32_t)__cvta_generic_to_shared(buf);

    if (t == 0) {
        asm volatile("mbarrier.init.shared.b64 [%0], 1;" :: "r"(mb0) : "memory");
        asm volatile("mbarrier.init.shared.b64 [%0], 1;" :: "r"(mb0 + 8) : "memory");
    }

    if (c < 32) {
        // ---- copy-through: t0-only, no __syncthreads needed ----
        if (t == 0) {
            asm volatile("mbarrier.arrive.expect_tx.shared.b64 _, [%0], %1;"
                         :: "r"(mb0), "r"(bytes0 + bytes1) : "memory");
            asm volatile("cp.async.bulk.shared::cta.global.mbarrier::complete_tx::bytes "
                         "[%0], [%1], %2, [%3];"
                         :: "r"(sb), "l"(src), "r"(bytes0 + bytes1), "r"(mb0) : "memory");
            mbar_wait(mb0);
            asm volatile("fence.proxy.async.shared::cta;" ::: "memory");
            asm volatile("cp.async.bulk.global.shared::cta.bulk_group [%0], [%1], %2;"
                         :: "l"(dst), "r"(sb), "r"(bytes0 + bytes1) : "memory");
            asm volatile("cp.async.bulk.commit_group;" ::: "memory");
            asm volatile("cp.async.bulk.wait_group 0;" ::: "memory");
        }
        return;
    }

    __syncthreads();   // init visible to all waiters
    if (t == 0) {
        // sub0: first 16 rows
        asm volatile("mbarrier.arrive.expect_tx.shared.b64 _, [%0], %1;"
                     :: "r"(mb0), "r"(bytes0) : "memory");
        asm volatile("cp.async.bulk.shared::cta.global.mbarrier::complete_tx::bytes "
                     "[%0], [%1], %2, [%3];"
                     :: "r"(sb), "l"(src), "r"(bytes0), "r"(mb0) : "memory");
        // sub1: remaining rows
        asm volatile("mbarrier.arrive.expect_tx.shared.b64 _, [%0], %1;"
                     :: "r"(mb0 + 8), "r"(bytes1) : "memory");
        asm volatile("cp.async.bulk.shared::cta.global.mbarrier::complete_tx::bytes "
                     "[%0], [%1], %2, [%3];"
                     :: "r"(sb + (uint32_t)bytes0),
                        "l"(src + (size_t)SUB0_ROWS * W_DIM), "r"(bytes1), "r"(mb0 + 8)
                     : "memory");
    }

    if (c < 80) {
        // 2x2: sub0 -> block rows [0,8); sub1 -> [8, nrows/2)
        mbar_wait(mb0);
        run_2x2(buf, dst, 0, SUB0_ROWS / 2, t);
        mbar_wait(mb0 + 8);
        run_2x2(buf, dst, SUB0_ROWS / 2, nrows >> 1, t);
    } else {
        // 4x4: sub0 -> block rows [0,4); sub1 -> [4, ceil(nrows/4))
        mbar_wait(mb0);
        run_4x4(buf, dst, 0, SUB0_ROWS / 4, nrows, t);
        mbar_wait(mb0 + 8);
        run_4x4(buf, dst, SUB0_ROWS / 4, (nrows + 3) >> 2, nrows, t);
    }
}

extern "C" void kernel_launch(void* const* d_in, const int* in_sizes, int n_in,
                              void* d_out, int out_size) {
    (void)in_sizes; (void)n_in; (void)out_size;
    const float* act = (const float*)d_in[0];
    float* out = (float*)d_out;
    // 16 batches * 128 channels * 4 quarter-chunks = 8192 CTAs
    block_relu_q2<<<8192, 128>>>(act, out);
}